// round 4
// baseline (speedup 1.0000x reference)
#include <cuda_runtime.h>
#include <cstdint>

#define NUM_HASHES   8
#define NUM_BUCKETS  16384
#define SHARD        96
#define HIDDEN       768
#define F4_PER_SHARD 24      // 96 floats / 4
#define F4_PER_TOKEN 192     // 768 floats / 4
#define LN_EPS       1e-6f

__constant__ unsigned int c_primes[NUM_HASHES] = {31u, 43u, 59u, 61u, 73u, 97u, 103u, 113u};

__global__ __launch_bounds__(256, 4)
void canine_emb_ln_kernel(const int* __restrict__ ids,
                          const float* __restrict__ tables,
                          const float* __restrict__ ln_scale,
                          const float* __restrict__ ln_bias,
                          float* __restrict__ out,
                          int n_tokens)
{
    const int warp = (blockIdx.x * blockDim.x + threadIdx.x) >> 5;
    const int lane = threadIdx.x & 31;
    if (warp >= n_tokens) return;

    // ids are int32 (JAX x64 disabled downcasts the declared int64).
    // All lanes read the same 4B id -> single transaction, broadcast.
    const unsigned int h32 = (unsigned int)(ids[warp] + 1);

    // Gather 6 float4 per lane (lane-major across the 192 float4 of a token).
    // Addresses are all computable up front -> ptxas front-batches the 6 LDGs
    // (high MLP) so DRAM/L2 latency overlaps.
    float4 vec[6];
    float sum = 0.f, sumsq = 0.f;
#pragma unroll 6
    for (int k = 0; k < 6; k++) {
        const int f = lane + 32 * k;            // float4 index within token [0,192)
        const int h = f / F4_PER_SHARD;         // which hash table [0,8)
        const int m = f % F4_PER_SHARD;         // float4 offset inside the 96-float row
        const unsigned int bucket = (h32 * c_primes[h]) & (NUM_BUCKETS - 1);
        const float4* row = reinterpret_cast<const float4*>(
            tables + (size_t)(h * NUM_BUCKETS + bucket) * SHARD);
        const float4 x = __ldg(row + m);
        vec[k] = x;
        sum   += x.x + x.y + x.z + x.w;
        sumsq += x.x * x.x + x.y * x.y + x.z * x.z + x.w * x.w;
    }

    // Warp-wide reduction of sum / sumsq.
#pragma unroll
    for (int o = 16; o > 0; o >>= 1) {
        sum   += __shfl_xor_sync(0xffffffffu, sum,   o);
        sumsq += __shfl_xor_sync(0xffffffffu, sumsq, o);
    }
    const float inv_n = 1.0f / (float)HIDDEN;
    const float mean  = sum * inv_n;
    const float var   = fmaxf(sumsq * inv_n - mean * mean, 0.0f);
    const float rstd  = rsqrtf(var + LN_EPS);

    float4* op = reinterpret_cast<float4*>(out + (size_t)warp * HIDDEN);
    const float4* sc = reinterpret_cast<const float4*>(ln_scale);
    const float4* bi = reinterpret_cast<const float4*>(ln_bias);

#pragma unroll 6
    for (int k = 0; k < 6; k++) {
        const int f = lane + 32 * k;
        const float4 s = __ldg(sc + f);
        const float4 b = __ldg(bi + f);
        const float4 x = vec[k];
        float4 r;
        r.x = fmaf((x.x - mean) * rstd, s.x, b.x);
        r.y = fmaf((x.y - mean) * rstd, s.y, b.y);
        r.z = fmaf((x.z - mean) * rstd, s.z, b.z);
        r.w = fmaf((x.w - mean) * rstd, s.w, b.w);
        // Streaming store: keep the 201 MB output stream from evicting the
        // 50 MB L2-resident table (which gets ~4x reuse).
        __stcs(op + f, r);
    }
}

extern "C" void kernel_launch(void* const* d_in, const int* in_sizes, int n_in,
                              void* d_out, int out_size)
{
    const int*   ids      = (const int*)d_in[0];     // [8, 8192] int32 (see note)
    const float* tables   = (const float*)d_in[1];   // [8, 16384, 96] f32
    const float* ln_scale = (const float*)d_in[2];   // [768]
    const float* ln_bias  = (const float*)d_in[3];   // [768]
    float*       out      = (float*)d_out;           // [8, 8192, 768] f32

    const int n_tokens = in_sizes[0];                // 65536
    const int warps_per_block = 8;                   // 256 threads
    const int blocks = (n_tokens + warps_per_block - 1) / warps_per_block;
    canine_emb_ln_kernel<<<blocks, warps_per_block * 32>>>(
        ids, tables, ln_scale, ln_bias, out, n_tokens);
}

// round 6
// speedup vs baseline: 1.0006x; 1.0006x over previous
#include <cuda_runtime.h>
#include <cstdint>

#define NUM_HASHES   8
#define NUM_BUCKETS  16384
#define SHARD        96
#define HIDDEN       768
#define LN_EPS       1e-6f

__global__ __launch_bounds__(256, 6)
void canine_emb_ln_kernel(const int* __restrict__ ids,
                          const float* __restrict__ tables,
                          const float* __restrict__ ln_scale,
                          const float* __restrict__ ln_bias,
                          float* __restrict__ out,
                          int n_tokens)
{
    const int warp = (blockIdx.x * blockDim.x + threadIdx.x) >> 5;
    const int lane = threadIdx.x & 31;
    if (warp >= n_tokens) return;

    // ids are int32 (JAX downcasts the declared int64).
    const unsigned int h32 = (unsigned int)(ids[warp] + 1);

    // Per-k compile-time tables (folded to immediates after full unroll).
    // f = lane + 32k spans at most 2 hash tables: h0 = floor(32k/24),
    // lane threshold TT = 24*(h0+1) - 32k. primes = {31,43,59,61,73,97,103,113}.
    const int      H0[6] = {0, 1, 2, 4, 5, 6};
    const int      TT[6] = {24, 16, 8, 24, 16, 8};
    const unsigned P0[6] = {31u, 43u, 59u, 73u, 97u, 103u};
    const unsigned P1[6] = {43u, 59u, 61u, 97u, 103u, 113u};

    const float4* t4 = reinterpret_cast<const float4*>(tables);

    // Pass 1: gather + accumulate moments. Do NOT hold the vectors.
    float sum = 0.f, sumsq = 0.f;
#pragma unroll
    for (int k = 0; k < 6; k++) {
        const int f = lane + 32 * k;
        const int hi = (lane >= TT[k]) ? 1 : 0;          // predicate, compile-time threshold
        const int h = H0[k] + hi;
        const unsigned prime  = hi ? P1[k] : P0[k];      // SEL of immediates, no LDC
        const unsigned bucket = (h32 * prime) & (NUM_BUCKETS - 1);
        const int idx = ((h << 14) | (int)bucket) * 24 + (f - 24 * h);
        const float4 x = __ldg(t4 + idx);
        sum   += x.x + x.y + x.z + x.w;
        sumsq += x.x * x.x + x.y * x.y + x.z * x.z + x.w * x.w;
    }

    // Warp reduction.
#pragma unroll
    for (int o = 16; o > 0; o >>= 1) {
        sum   += __shfl_xor_sync(0xffffffffu, sum,   o);
        sumsq += __shfl_xor_sync(0xffffffffu, sumsq, o);
    }
    const float inv_n = 1.0f / (float)HIDDEN;
    const float mean  = sum * inv_n;
    const float var   = fmaxf(sumsq * inv_n - mean * mean, 0.0f);
    const float rstd  = rsqrtf(var + LN_EPS);

    float4* op = reinterpret_cast<float4*>(out + (size_t)warp * HIDDEN);
    const float4* sc = reinterpret_cast<const float4*>(ln_scale);
    const float4* bi = reinterpret_cast<const float4*>(ln_bias);

    // Pass 2: reload the gathered rows (L1 hits — same warp touched them
    // ~150 cycles ago), normalize, streaming-store. asm volatile prevents
    // CSE with pass 1, which would pin 24 registers and cap occupancy.
#pragma unroll
    for (int k = 0; k < 6; k++) {
        const int f = lane + 32 * k;
        const int hi = (lane >= TT[k]) ? 1 : 0;
        const int h = H0[k] + hi;
        const unsigned prime  = hi ? P1[k] : P0[k];
        const unsigned bucket = (h32 * prime) & (NUM_BUCKETS - 1);
        const int idx = ((h << 14) | (int)bucket) * 24 + (f - 24 * h);
        const float4* p = t4 + idx;
        float4 x;
        asm volatile("ld.global.nc.v4.f32 {%0,%1,%2,%3}, [%4];"
                     : "=f"(x.x), "=f"(x.y), "=f"(x.z), "=f"(x.w)
                     : "l"(p));
        const float4 s = __ldg(sc + f);
        const float4 b = __ldg(bi + f);
        float4 r;
        r.x = fmaf((x.x - mean) * rstd, s.x, b.x);
        r.y = fmaf((x.y - mean) * rstd, s.y, b.y);
        r.z = fmaf((x.z - mean) * rstd, s.z, b.z);
        r.w = fmaf((x.w - mean) * rstd, s.w, b.w);
        // Streaming store: protect the 50 MB L2-resident table (~4x reuse)
        // from the 201 MB output stream.
        __stcs(op + f, r);
    }
}

extern "C" void kernel_launch(void* const* d_in, const int* in_sizes, int n_in,
                              void* d_out, int out_size)
{
    const int*   ids      = (const int*)d_in[0];     // [8, 8192] int32
    const float* tables   = (const float*)d_in[1];   // [8, 16384, 96] f32
    const float* ln_scale = (const float*)d_in[2];   // [768]
    const float* ln_bias  = (const float*)d_in[3];   // [768]
    float*       out      = (float*)d_out;           // [8, 8192, 768] f32

    const int n_tokens = in_sizes[0];                // 65536
    const int warps_per_block = 8;                   // 256 threads
    const int blocks = (n_tokens + warps_per_block - 1) / warps_per_block;
    canine_emb_ln_kernel<<<blocks, warps_per_block * 32>>>(
        ids, tables, ln_scale, ln_bias, out, n_tokens);
}